// round 2
// baseline (speedup 1.0000x reference)
#include <cuda_runtime.h>
#include <cstddef>

// Axial attention on a 7x7 grid.
// out[n,c,h,w] = sum_j p[n,h,w,j]   * vH[(n*7+w), c, j]
//             + sum_y p[n,h,w,7+y] * vW[(n*7+h), c, y]
// where p = softmax over 14 of [eH (diag-masked, transposed), eW].

#define NEGV (-1e20f)
#define MAXN 1024

// softmax probabilities scratch: p[n][h*7+w][14]
__device__ float g_p[(size_t)MAXN * 49 * 14];

// ---------------------------------------------------------------------------
// Phase 1: logits + softmax per n. One block per n.
// smem: q slice (7*7*64) + k slice (7*64*7) + 686 logits. Two passes (H then W)
// reuse the same q/k buffers to stay under the 48KB static smem limit.
// ---------------------------------------------------------------------------
__global__ __launch_bounds__(256) void axattn_phase1(
    const float* __restrict__ qH, const float* __restrict__ kH,
    const float* __restrict__ qW, const float* __restrict__ kW)
{
    __shared__ float qs[3136];
    __shared__ float ks[3136];
    __shared__ float lg[49 * 14];

    const int n = blockIdx.x;
    const int tid = threadIdx.x;

    // ---- pass 1: eH ----
    {
        const float4* q4 = (const float4*)(qH + (size_t)n * 3136);
        const float4* k4 = (const float4*)(kH + (size_t)n * 3136);
        for (int i = tid; i < 784; i += 256) {
            ((float4*)qs)[i] = q4[i];
            ((float4*)ks)[i] = k4[i];
        }
    }
    __syncthreads();
    for (int t = tid; t < 343; t += 256) {
        int h = t / 49, rem = t % 49, w = rem / 7, j = rem % 7;
        const float* qr = qs + w * 448 + h * 64;   // qHr[n,w,h,:]
        const float* kr = ks + w * 448 + j;        // kHr[n,w,:,j]
        float acc = 0.f;
        #pragma unroll
        for (int c = 0; c < 64; c++) acc += qr[c] * kr[c * 7];
        lg[(h * 7 + w) * 14 + j] = (h == j) ? NEGV : acc;
    }
    __syncthreads();

    // ---- pass 2: eW ----
    {
        const float4* q4 = (const float4*)(qW + (size_t)n * 3136);
        const float4* k4 = (const float4*)(kW + (size_t)n * 3136);
        for (int i = tid; i < 784; i += 256) {
            ((float4*)qs)[i] = q4[i];
            ((float4*)ks)[i] = k4[i];
        }
    }
    __syncthreads();
    for (int t = tid; t < 343; t += 256) {
        int h = t / 49, rem = t % 49, w = rem / 7, y = rem % 7;
        const float* qr = qs + h * 448 + w * 64;   // qWr[n,h,w,:]
        const float* kr = ks + h * 448 + y;        // kWr[n,h,:,y]
        float acc = 0.f;
        #pragma unroll
        for (int c = 0; c < 64; c++) acc += qr[c] * kr[c * 7];
        lg[(h * 7 + w) * 14 + 7 + y] = acc;
    }
    __syncthreads();

    // ---- softmax over 14, one thread per (h,w) ----
    if (tid < 49) {
        float* row = lg + tid * 14;
        float m = row[0];
        #pragma unroll
        for (int s = 1; s < 14; s++) m = fmaxf(m, row[s]);
        float e[14];
        float sum = 0.f;
        #pragma unroll
        for (int s = 0; s < 14; s++) { e[s] = __expf(row[s] - m); sum += e[s]; }
        float inv = 1.f / sum;
        #pragma unroll
        for (int s = 0; s < 14; s++) row[s] = e[s] * inv;
    }
    __syncthreads();

    float* gp = g_p + (size_t)n * 686;
    for (int i = tid; i < 686; i += 256) gp[i] = lg[i];
}

// ---------------------------------------------------------------------------
// Phase 2: PV contraction. Block = (c-chunk of 64, n). Each block stages its
// vH/vW chunk into smem with j padded 7->8 (row stride 516 floats: banks for
// the 7 w/h rows land at 4*w mod 32 -> conflict-free float4 reads), keeps the
// 14 softmax weights of its (h,w) in registers, and streams 64 channels.
// ---------------------------------------------------------------------------
#define CHUNK 64
#define VSTRIDE 516   // CHUNK*8 + 4 ; %4==0 for float4, %32==4 for banks

__global__ __launch_bounds__(256) void axattn_phase2(
    const float* __restrict__ vH, const float* __restrict__ vW,
    float* __restrict__ out, int Cv)
{
    __shared__ float vh_s[7 * VSTRIDE];
    __shared__ float vw_s[7 * VSTRIDE];

    const int n  = blockIdx.y;
    const int cc = blockIdx.x;
    const int c0 = cc * CHUNK;
    const int tid = threadIdx.x;

    const size_t vsz = (size_t)Cv * 7;                 // per (b) slice stride
    const float* vhb = vH + (size_t)n * 7 * vsz + (size_t)c0 * 7;
    const float* vwb = vW + (size_t)n * 7 * vsz + (size_t)c0 * 7;

    // Stage chunk: 7 contiguous 448-float rows per tensor, repacked to stride-8.
    for (int i = tid; i < 7 * 112; i += 256) {
        int w  = i / 112;
        int r4 = (i % 112) * 4;          // element offset within the 448 block
        if (c0 + r4 / 7 < Cv) {
            float4 a = *(const float4*)(vhb + (size_t)w * vsz + r4);
            float4 b = *(const float4*)(vwb + (size_t)w * vsz + r4);
            float va[4] = {a.x, a.y, a.z, a.w};
            float vb[4] = {b.x, b.y, b.z, b.w};
            #pragma unroll
            for (int t = 0; t < 4; t++) {
                int r = r4 + t;
                int c = r / 7, j = r % 7;
                vh_s[w * VSTRIDE + c * 8 + j] = va[t];
                vw_s[w * VSTRIDE + c * 8 + j] = vb[t];
            }
        }
    }

    // Per-thread softmax weights: thread = (g, hw), g in [0,5), hw in [0,49).
    const int hw = tid % 49;
    const int g  = tid / 49;
    const bool active = (g < 5);
    const int h = hw / 7, w = hw % 7;

    float p[14];
    if (active) {
        const float* gp = g_p + (size_t)n * 686 + hw * 14;
        #pragma unroll
        for (int s = 0; s < 14; s++) p[s] = gp[s];
    }
    __syncthreads();

    if (active) {
        float* ob = out + (size_t)n * Cv * 49 + (size_t)c0 * 49 + hw;
        const float4* vh4 = (const float4*)(vh_s + w * VSTRIDE);
        const float4* vw4 = (const float4*)(vw_s + h * VSTRIDE);
        #pragma unroll 4
        for (int c = g; c < CHUNK; c += 5) {
            if (c0 + c >= Cv) break;
            float4 a0 = vh4[c * 2], a1 = vh4[c * 2 + 1];
            float4 b0 = vw4[c * 2], b1 = vw4[c * 2 + 1];
            float acc = p[0] * a0.x + p[1] * a0.y + p[2]  * a0.z + p[3]  * a0.w
                      + p[4] * a1.x + p[5] * a1.y + p[6]  * a1.z
                      + p[7] * b0.x + p[8] * b0.y + p[9]  * b0.z + p[10] * b0.w
                      + p[11] * b1.x + p[12] * b1.y + p[13] * b1.z;
            ob[(size_t)c * 49] = acc;
        }
    }
}

extern "C" void kernel_launch(void* const* d_in, const int* in_sizes, int n_in,
                              void* d_out, int out_size)
{
    const float* qH = (const float*)d_in[0];
    const float* kH = (const float*)d_in[1];
    const float* vH = (const float*)d_in[2];
    const float* qW = (const float*)d_in[3];
    const float* kW = (const float*)d_in[4];
    const float* vW = (const float*)d_in[5];

    // qH has N*7*7*64 elements; vH has N*49*Cv elements.
    int N  = in_sizes[0] / (49 * 64);
    int Cv = in_sizes[2] / (N * 49);

    axattn_phase1<<<N, 256>>>(qH, kH, qW, kW);

    dim3 g2((Cv + CHUNK - 1) / CHUNK, N);
    axattn_phase2<<<g2, 256>>>(vH, vW, (float*)d_out, Cv);
}

// round 3
// speedup vs baseline: 1.0311x; 1.0311x over previous
#include <cuda_runtime.h>
#include <cstddef>

// Axial attention on a 7x7 grid (N=512, Cq=64, Cv=512).
// out[n,c,h,w] = sum_j p[n,h,w,j]   * vH[(n*7+w), c, j]
//             + sum_y p[n,h,w,7+y] * vW[(n*7+h), c, y]
// p = softmax over 14 of [eH (diag-masked, transposed), eW].

#define NEGV (-1e20f)
#define MAXN 1024

// softmax probabilities scratch: p[n][h*7+w][14]
__device__ float g_p[(size_t)MAXN * 49 * 14];

// ---------------------------------------------------------------------------
// Phase 1: logits + softmax per n. One block per n, 256 threads.
// Both q and k slices are staged in smem in [slice][row][c] layout with
// bank-spreading pads (strides 484 / 68, both == 4 mod 32), k transposed so
// the dot product is pure contiguous float4 reads.
// ---------------------------------------------------------------------------
#define ASTRIDE 484   // slice stride (floats), 484 % 32 == 4
#define RSTRIDE 68    // row   stride (floats),  68 % 32 == 4

__global__ __launch_bounds__(256) void axattn_phase1(
    const float* __restrict__ qH, const float* __restrict__ kH,
    const float* __restrict__ qW, const float* __restrict__ kW)
{
    __shared__ float qs[7 * ASTRIDE];   // [a][row][c]
    __shared__ float kt[7 * ASTRIDE];   // [a][j][c]  (transposed k)
    __shared__ float lg[49 * 14];

    const int n = blockIdx.x;
    const int tid = threadIdx.x;

    #pragma unroll
    for (int pass = 0; pass < 2; pass++) {
        const float* qsrc = (pass == 0 ? qH : qW) + (size_t)n * 3136;
        const float* ksrc = (pass == 0 ? kH : kW) + (size_t)n * 3136;

        if (pass == 1) __syncthreads();   // protect buffers from pass-0 readers

        // stage q: global [a][row][c] -> qs[a*AS + row*RS + c]
        for (int i = tid; i < 3136; i += 256) {
            int a = i / 448, r = i % 448, row = r / 64, c = r % 64;
            qs[a * ASTRIDE + row * RSTRIDE + c] = qsrc[i];
        }
        // stage k with transpose: global [a][c][j] -> kt[a*AS + j*RS + c]
        for (int i = tid; i < 3136; i += 256) {
            int a = i / 448, r = i % 448, c = r / 7, j = r % 7;
            kt[a * ASTRIDE + j * RSTRIDE + c] = ksrc[i];
        }
        __syncthreads();

        // one thread per logit
        for (int t = tid; t < 343; t += 256) {
            int h = t / 49, rem = t % 49, w = rem / 7, j = rem % 7;
            // pass 0 (H): slice a=w, q-row=h  ; pass 1 (W): slice a=h, q-row=w
            int a   = pass == 0 ? w : h;
            int row = pass == 0 ? h : w;
            const float4* q4 = (const float4*)(qs + a * ASTRIDE + row * RSTRIDE);
            const float4* k4 = (const float4*)(kt + a * ASTRIDE + j   * RSTRIDE);
            float4 acc = make_float4(0.f, 0.f, 0.f, 0.f);
            #pragma unroll
            for (int kk = 0; kk < 16; kk++) {
                float4 x = q4[kk], y = k4[kk];
                acc.x += x.x * y.x; acc.y += x.y * y.y;
                acc.z += x.z * y.z; acc.w += x.w * y.w;
            }
            float v = (acc.x + acc.y) + (acc.z + acc.w);
            if (pass == 0) {
                lg[(h * 7 + w) * 14 + j] = (h == j) ? NEGV : v;
            } else {
                lg[(h * 7 + w) * 14 + 7 + j] = v;
            }
        }
    }
    __syncthreads();

    // softmax over 14, one thread per (h,w)
    if (tid < 49) {
        float* rowp = lg + tid * 14;
        float m = rowp[0];
        #pragma unroll
        for (int s = 1; s < 14; s++) m = fmaxf(m, rowp[s]);
        float e[14];
        float sum = 0.f;
        #pragma unroll
        for (int s = 0; s < 14; s++) { e[s] = __expf(rowp[s] - m); sum += e[s]; }
        float inv = 1.f / sum;
        #pragma unroll
        for (int s = 0; s < 14; s++) rowp[s] = e[s] * inv;
    }
    __syncthreads();

    float* gp = g_p + (size_t)n * 686;
    for (int i = tid; i < 686; i += 256) gp[i] = lg[i];
}

// ---------------------------------------------------------------------------
// Phase 2: PV contraction. Block = (c-chunk of 64, n).
// Thread map: g = tid/64 (4 groups), hw = tid%64 (active hw<49).
// Every warp carries a constant g, so in the channel loop ALL lanes read the
// SAME channel c => vh/vw LDS.128 has <=7 unique addresses on disjoint bank
// quads (VSTRIDE=516) => 1 wavefront per load instead of 4.
// ---------------------------------------------------------------------------
#define CHUNK 64
#define VSTRIDE 516   // CHUNK*8 + 4 ; %4==0 for float4, %32==4 for banks

__global__ __launch_bounds__(256) void axattn_phase2(
    const float* __restrict__ vH, const float* __restrict__ vW,
    float* __restrict__ out, int Cv)
{
    __shared__ float vh_s[7 * VSTRIDE];
    __shared__ float vw_s[7 * VSTRIDE];
    __shared__ float ps[49 * 14];

    const int n  = blockIdx.y;
    const int c0 = blockIdx.x * CHUNK;
    const int tid = threadIdx.x;

    const size_t vsz = (size_t)Cv * 7;                 // per (b) slice stride
    const float* vhb = vH + (size_t)n * 7 * vsz + (size_t)c0 * 7;
    const float* vwb = vW + (size_t)n * 7 * vsz + (size_t)c0 * 7;

    // Stage v chunk: 7 contiguous 448-float rows per tensor, repacked to
    // [w][c*8 + j] (j padded 7->8).
    for (int i = tid; i < 7 * 112; i += 256) {
        int w  = i / 112;
        int r4 = (i % 112) * 4;          // element offset within the 448 block
        if (c0 + r4 / 7 < Cv) {
            float4 a = *(const float4*)(vhb + (size_t)w * vsz + r4);
            float4 b = *(const float4*)(vwb + (size_t)w * vsz + r4);
            float va[4] = {a.x, a.y, a.z, a.w};
            float vb[4] = {b.x, b.y, b.z, b.w};
            #pragma unroll
            for (int t = 0; t < 4; t++) {
                int r = r4 + t;
                int c = r / 7, j = r % 7;
                vh_s[w * VSTRIDE + c * 8 + j] = va[t];
                vw_s[w * VSTRIDE + c * 8 + j] = vb[t];
            }
        }
    }
    // Stage softmax probabilities
    {
        const float* gp = g_p + (size_t)n * 686;
        for (int i = tid; i < 686; i += 256) ps[i] = gp[i];
    }
    __syncthreads();

    const int hw = tid & 63;       // 0..63, active < 49
    const int g  = tid >> 6;       // 0..3 : constant within each warp
    if (hw < 49) {
        const int h = hw / 7, w = hw % 7;
        float p[14];
        #pragma unroll
        for (int s = 0; s < 14; s++) p[s] = ps[hw * 14 + s];

        const float4* vh4 = (const float4*)(vh_s + w * VSTRIDE);
        const float4* vw4 = (const float4*)(vw_s + h * VSTRIDE);
        const int cbase = g * 16;
        const int cmax  = Cv - c0;
        float* ob = out + (size_t)n * Cv * 49 + (size_t)(c0 + cbase) * 49 + hw;

        #pragma unroll 8
        for (int k = 0; k < 16; k++) {
            int c = cbase + k;                  // uniform across the warp
            if (c >= cmax) break;
            float4 a0 = vh4[2 * c], a1 = vh4[2 * c + 1];
            float4 b0 = vw4[2 * c], b1 = vw4[2 * c + 1];
            float acc = p[0] * a0.x + p[1] * a0.y + p[2]  * a0.z + p[3]  * a0.w
                      + p[4] * a1.x + p[5] * a1.y + p[6]  * a1.z
                      + p[7] * b0.x + p[8] * b0.y + p[9]  * b0.z + p[10] * b0.w
                      + p[11] * b1.x + p[12] * b1.y + p[13] * b1.z;
            ob[(size_t)k * 49] = acc;
        }
    }
}

extern "C" void kernel_launch(void* const* d_in, const int* in_sizes, int n_in,
                              void* d_out, int out_size)
{
    const float* qH = (const float*)d_in[0];
    const float* kH = (const float*)d_in[1];
    const float* vH = (const float*)d_in[2];
    const float* qW = (const float*)d_in[3];
    const float* kW = (const float*)d_in[4];
    const float* vW = (const float*)d_in[5];

    int N  = in_sizes[0] / (49 * 64);
    int Cv = in_sizes[2] / (N * 49);

    axattn_phase1<<<N, 256>>>(qH, kH, qW, kW);

    dim3 g2((Cv + CHUNK - 1) / CHUNK, N);
    axattn_phase2<<<g2, 256>>>(vH, vW, (float*)d_out, Cv);
}